// round 2
// baseline (speedup 1.0000x reference)
#include <cuda_runtime.h>
#include <cuda_bf16.h>

// Problem constants
#define NN   50000
#define EE   1600000
#define HH   8
#define FF   16
#define INF  256
#define HF   128          // H*F
#define SLOPE 0.2f

// ---------------- scratch (static device globals; no allocation) -------------
__device__ float g_feat[NN * HF];      // 25.6 MB
__device__ float g_el[NN * HH];
__device__ float g_er[NN * HH];
__device__ int   g_cnt[NN];
__device__ int   g_off[NN + 1];
__device__ int   g_cursor[NN];
__device__ int   g_src32[EE];
__device__ int   g_dst32[EE];
__device__ int   g_csr_src[EE];        // src node id per edge, grouped by dst
__device__ int   g_is64;

// ---------------- kernel A: detect index dtype -------------------------------
// int64 values are < 50000 -> all high 32-bit words zero.
// int32 data read as uint2 puts the NEXT random element in .y -> nonzero.
__global__ void detect_kernel(const void* __restrict__ dstp) {
    if (threadIdx.x == 0 && blockIdx.x == 0) {
        const uint2* p = (const uint2*)dstp;
        unsigned any = 0;
        for (int i = 0; i < 256; i++) any |= p[i].y;
        g_is64 = (any == 0u) ? 1 : 0;
    }
}

// ---------------- kernel B: normalize indices to int32 + dst histogram -------
__global__ void convert_hist_kernel(const void* __restrict__ srcp,
                                    const void* __restrict__ dstp) {
    int stride = gridDim.x * blockDim.x;
    int is64 = g_is64;
    for (int i = blockIdx.x * blockDim.x + threadIdx.x; i < EE; i += stride) {
        int s, d;
        if (is64) {
            s = (int)((const long long*)srcp)[i];
            d = (int)((const long long*)dstp)[i];
        } else {
            s = ((const int*)srcp)[i];
            d = ((const int*)dstp)[i];
        }
        s = min(max(s, 0), NN - 1);
        d = min(max(d, 0), NN - 1);
        g_src32[i] = s;
        g_dst32[i] = d;
        atomicAdd(&g_cnt[d], 1);
    }
}

// ---------------- kernel 0: zero counters -----------------------------------
__global__ void zero_cnt_kernel() {
    int i = blockIdx.x * blockDim.x + threadIdx.x;
    if (i < NN) g_cnt[i] = 0;
}

// ---------------- kernel 1: feat = x @ W  (32x128 tile, 4x4 per thread) ------
__global__ __launch_bounds__(256) void gemm_kernel(const float* __restrict__ x,
                                                   const float* __restrict__ W) {
    __shared__ float xs[32][32];        // [row][k]
    __shared__ float ws[32][HF];        // [k][col]
    int tid  = threadIdx.x;
    int row0 = blockIdx.x * 32;
    int tcol = tid & 31;                // column group (4 cols)
    int trow = tid >> 5;                // row group (4 rows); == warp id

    float acc[4][4];
#pragma unroll
    for (int r = 0; r < 4; r++)
#pragma unroll
        for (int c = 0; c < 4; c++) acc[r][c] = 0.f;

    for (int k0 = 0; k0 < INF; k0 += 32) {
#pragma unroll
        for (int i = 0; i < 4; i++) {
            int idx = tid + i * 256;
            int r = idx >> 5, k = idx & 31;
            int gr = row0 + r;
            xs[r][k] = (gr < NN) ? x[(long)gr * INF + k0 + k] : 0.f;
        }
#pragma unroll
        for (int i = 0; i < 4; i++) {
            int idx = tid + i * 256;           // float4 index
            int k = idx >> 5, c4 = idx & 31;
            ((float4*)ws[k])[c4] = ((const float4*)(W + (long)(k0 + k) * HF))[c4];
        }
        __syncthreads();
#pragma unroll
        for (int kk = 0; kk < 32; kk++) {
            float4 b = ((float4*)ws[kk])[tcol];
            float a0 = xs[trow * 4 + 0][kk];
            float a1 = xs[trow * 4 + 1][kk];
            float a2 = xs[trow * 4 + 2][kk];
            float a3 = xs[trow * 4 + 3][kk];
            acc[0][0] += a0 * b.x; acc[0][1] += a0 * b.y; acc[0][2] += a0 * b.z; acc[0][3] += a0 * b.w;
            acc[1][0] += a1 * b.x; acc[1][1] += a1 * b.y; acc[1][2] += a1 * b.z; acc[1][3] += a1 * b.w;
            acc[2][0] += a2 * b.x; acc[2][1] += a2 * b.y; acc[2][2] += a2 * b.z; acc[2][3] += a2 * b.w;
            acc[3][0] += a3 * b.x; acc[3][1] += a3 * b.y; acc[3][2] += a3 * b.z; acc[3][3] += a3 * b.w;
        }
        __syncthreads();
    }
#pragma unroll
    for (int r = 0; r < 4; r++) {
        int gr = row0 + trow * 4 + r;
        if (gr < NN) {
            float4 v = make_float4(acc[r][0], acc[r][1], acc[r][2], acc[r][3]);
            ((float4*)(g_feat + (long)gr * HF))[tcol] = v;
        }
    }
}

// ---------------- kernel 2: el/er per node (one warp per node) ---------------
__global__ __launch_bounds__(256) void elr_kernel(const float* __restrict__ al,
                                                  const float* __restrict__ ar) {
    int gtid = blockIdx.x * blockDim.x + threadIdx.x;
    int n    = gtid >> 5;
    int lane = gtid & 31;
    if (n >= NN) return;
    float4 f = ((const float4*)g_feat)[n * 32 + lane];
    float4 a = ((const float4*)al)[lane];
    float4 b = ((const float4*)ar)[lane];
    float sl = f.x * a.x + f.y * a.y + f.z * a.z + f.w * a.w;
    float sr = f.x * b.x + f.y * b.y + f.z * b.z + f.w * b.w;
    sl += __shfl_xor_sync(0xffffffffu, sl, 1);
    sl += __shfl_xor_sync(0xffffffffu, sl, 2);
    sr += __shfl_xor_sync(0xffffffffu, sr, 1);
    sr += __shfl_xor_sync(0xffffffffu, sr, 2);
    if ((lane & 3) == 0) {
        g_el[n * HH + (lane >> 2)] = sl;
        g_er[n * HH + (lane >> 2)] = sr;
    }
}

// ---------------- kernel 4: exclusive scan (single block) --------------------
__global__ void scan_kernel() {
    __shared__ int sh[1024];
    __shared__ int carry;
    if (threadIdx.x == 0) carry = 0;
    __syncthreads();
    for (int base = 0; base < NN; base += 1024) {
        int i = base + threadIdx.x;
        int v = (i < NN) ? g_cnt[i] : 0;
        sh[threadIdx.x] = v;
        __syncthreads();
        for (int s = 1; s < 1024; s <<= 1) {
            int t = (threadIdx.x >= s) ? sh[threadIdx.x - s] : 0;
            __syncthreads();
            sh[threadIdx.x] += t;
            __syncthreads();
        }
        int excl = sh[threadIdx.x] - v + carry;
        if (i < NN) { g_off[i] = excl; g_cursor[i] = excl; }
        __syncthreads();
        if (threadIdx.x == 1023) carry += sh[1023];
        __syncthreads();
    }
    if (threadIdx.x == 0) g_off[NN] = carry;
}

// ---------------- kernel 5: scatter edges into CSR ---------------------------
__global__ void scatter_kernel() {
    int stride = gridDim.x * blockDim.x;
    for (int i = blockIdx.x * blockDim.x + threadIdx.x; i < EE; i += stride) {
        int d = g_dst32[i];
        int p = atomicAdd(&g_cursor[d], 1);
        g_csr_src[p] = g_src32[i];
    }
}

// ---------------- kernel 6: fused softmax-aggregate + classifier -------------
// One warp per destination node. Lanes cover the 128 feat columns as float4;
// head of lane l is l/4. Lanes 0..7 own the 8 per-head exp/sum computations.
__global__ __launch_bounds__(256) void agg_kernel(const float* __restrict__ bias,
                                                  float* __restrict__ out) {
    int gtid = blockIdx.x * blockDim.x + threadIdx.x;
    int n    = gtid >> 5;
    int lane = gtid & 31;
    if (n >= NN) return;
    int h = lane >> 2;

    float ern = (lane < 8) ? g_er[n * HH + lane] : 0.f;
    int beg = g_off[n], end = g_off[n + 1];

    float4 acc = make_float4(0.f, 0.f, 0.f, 0.f);
    float ssum = 0.f;

    for (int i0 = beg; i0 < end; i0 += 32) {
        int s = (i0 + lane < end) ? g_csr_src[i0 + lane] : 0;
        int cnt = min(32, end - i0);
        for (int j = 0; j < cnt; j++) {
            int sv = __shfl_sync(0xffffffffu, s, j);
            float exv = 0.f;
            if (lane < 8) {
                float e = g_el[sv * HH + lane] + ern;
                e = fmaxf(e, 0.f) + SLOPE * fminf(e, 0.f);
                exv = __expf(e);
                ssum += exv;
            }
            float exh = __shfl_sync(0xffffffffu, exv, h);
            float4 f = ((const float4*)g_feat)[sv * 32 + lane];
            acc.x += exh * f.x;
            acc.y += exh * f.y;
            acc.z += exh * f.z;
            acc.w += exh * f.w;
        }
    }
    float sh  = __shfl_sync(0xffffffffu, ssum, h);
    float inv = 1.f / fmaxf(sh, 1e-9f);
    float v0 = acc.x * inv, v1 = acc.y * inv, v2 = acc.z * inv, v3 = acc.w * inv;
    // sum across 8 heads (lanes at stride 4 hold the same f-slot)
#pragma unroll
    for (int d = 4; d < 32; d <<= 1) {
        v0 += __shfl_xor_sync(0xffffffffu, v0, d);
        v1 += __shfl_xor_sync(0xffffffffu, v1, d);
        v2 += __shfl_xor_sync(0xffffffffu, v2, d);
        v3 += __shfl_xor_sync(0xffffffffu, v3, d);
    }
    if (lane < 4) {
        float b0 = 0.f, b1 = 0.f, b2 = 0.f, b3 = 0.f;
#pragma unroll
        for (int hh = 0; hh < HH; hh++) {
            b0 += bias[hh * FF + lane * 4 + 0];
            b1 += bias[hh * FF + lane * 4 + 1];
            b2 += bias[hh * FF + lane * 4 + 2];
            b3 += bias[hh * FF + lane * 4 + 3];
        }
        float4 o;
        o.x = (v0 + b0) * 0.125f;
        o.y = (v1 + b1) * 0.125f;
        o.z = (v2 + b2) * 0.125f;
        o.w = (v3 + b3) * 0.125f;
        ((float4*)out)[n * 4 + lane] = o;
    }
}

// ---------------- launch ------------------------------------------------------
extern "C" void kernel_launch(void* const* d_in, const int* in_sizes, int n_in,
                              void* d_out, int out_size) {
    const float* x    = (const float*)d_in[0];
    const float* W    = (const float*)d_in[1];
    const float* al   = (const float*)d_in[2];
    const float* ar   = (const float*)d_in[3];
    const float* bias = (const float*)d_in[4];
    const void*  src  = d_in[5];
    const void*  dst  = d_in[6];
    float* out = (float*)d_out;

    detect_kernel<<<1, 32>>>(dst);
    zero_cnt_kernel<<<(NN + 255) / 256, 256>>>();
    convert_hist_kernel<<<2048, 256>>>(src, dst);
    gemm_kernel<<<(NN + 31) / 32, 256>>>(x, W);
    elr_kernel<<<(NN * 32 + 255) / 256, 256>>>(al, ar);
    scan_kernel<<<1, 1024>>>();
    scatter_kernel<<<2048, 256>>>();
    agg_kernel<<<(NN * 32 + 255) / 256, 256>>>(bias, out);
}

// round 4
// speedup vs baseline: 1.2517x; 1.2517x over previous
#include <cuda_runtime.h>
#include <cuda_fp16.h>

#define NN   50000
#define EE   1600000
#define HH   8
#define FF   16
#define INF  256
#define HF   128
#define SLOPE 0.2f

// ---------------- scratch ----------------------------------------------------
__device__ __align__(16) __half g_feath[NN * HF];   // 12.8 MB
__device__ float g_el[NN * HH];
__device__ float g_er[NN * HH];
__device__ float g_mbias[FF];
__device__ int   g_cnt[NN];
__device__ int   g_off[NN + 1];
__device__ int   g_cursor[NN];
__device__ int   g_src32[EE];
__device__ int   g_dst32[EE];
__device__ int   g_csr_src[EE];
__device__ int   g_is64;

// ---------------- detect index dtype -----------------------------------------
__global__ void detect_kernel(const void* __restrict__ dstp) {
    if (threadIdx.x == 0 && blockIdx.x == 0) {
        const uint2* p = (const uint2*)dstp;
        unsigned any = 0;
        for (int i = 0; i < 256; i++) any |= p[i].y;
        g_is64 = (any == 0u) ? 1 : 0;
    }
}

// ---------------- zero counters + mean-bias ----------------------------------
__global__ void zero_cnt_kernel(const float* __restrict__ bias) {
    int i = blockIdx.x * blockDim.x + threadIdx.x;
    if (i < NN) g_cnt[i] = 0;
    if (i < FF) {
        float s = 0.f;
#pragma unroll
        for (int h = 0; h < HH; h++) s += bias[h * FF + i];
        g_mbias[i] = 0.125f * s;
    }
}

// ---------------- normalize indices + dst histogram --------------------------
__global__ void convert_hist_kernel(const void* __restrict__ srcp,
                                    const void* __restrict__ dstp) {
    int stride = gridDim.x * blockDim.x;
    int is64 = g_is64;
    for (int i = blockIdx.x * blockDim.x + threadIdx.x; i < EE; i += stride) {
        int s, d;
        if (is64) {
            s = (int)((const long long*)srcp)[i];
            d = (int)((const long long*)dstp)[i];
        } else {
            s = ((const int*)srcp)[i];
            d = ((const int*)dstp)[i];
        }
        s = min(max(s, 0), NN - 1);
        d = min(max(d, 0), NN - 1);
        g_src32[i] = s;
        g_dst32[i] = d;
        atomicAdd(&g_cnt[d], 1);
    }
}

// ---------------- GEMM + fused el/er + fp16 feat store ------------------------
__global__ __launch_bounds__(256) void gemm_kernel(const float* __restrict__ x,
                                                   const float* __restrict__ W,
                                                   const float* __restrict__ al,
                                                   const float* __restrict__ ar) {
    __shared__ float xs[32][32];
    __shared__ float ws[32][HF];
    int tid  = threadIdx.x;
    int row0 = blockIdx.x * 32;
    int tcol = tid & 31;
    int trow = tid >> 5;

    float acc[4][4];
#pragma unroll
    for (int r = 0; r < 4; r++)
#pragma unroll
        for (int c = 0; c < 4; c++) acc[r][c] = 0.f;

    for (int k0 = 0; k0 < INF; k0 += 32) {
#pragma unroll
        for (int i = 0; i < 4; i++) {
            int idx = tid + i * 256;
            int r = idx >> 5, k = idx & 31;
            int gr = row0 + r;
            xs[r][k] = (gr < NN) ? x[(long)gr * INF + k0 + k] : 0.f;
        }
#pragma unroll
        for (int i = 0; i < 4; i++) {
            int idx = tid + i * 256;
            int k = idx >> 5, c4 = idx & 31;
            ((float4*)ws[k])[c4] = ((const float4*)(W + (long)(k0 + k) * HF))[c4];
        }
        __syncthreads();
#pragma unroll
        for (int kk = 0; kk < 32; kk++) {
            float4 b = ((float4*)ws[kk])[tcol];
            float a0 = xs[trow * 4 + 0][kk];
            float a1 = xs[trow * 4 + 1][kk];
            float a2 = xs[trow * 4 + 2][kk];
            float a3 = xs[trow * 4 + 3][kk];
            acc[0][0] += a0 * b.x; acc[0][1] += a0 * b.y; acc[0][2] += a0 * b.z; acc[0][3] += a0 * b.w;
            acc[1][0] += a1 * b.x; acc[1][1] += a1 * b.y; acc[1][2] += a1 * b.z; acc[1][3] += a1 * b.w;
            acc[2][0] += a2 * b.x; acc[2][1] += a2 * b.y; acc[2][2] += a2 * b.z; acc[2][3] += a2 * b.w;
            acc[3][0] += a3 * b.x; acc[3][1] += a3 * b.y; acc[3][2] += a3 * b.z; acc[3][3] += a3 * b.w;
        }
        __syncthreads();
    }

    // epilogue: fp16 feat store + fused el/er (from exact fp32 accumulators)
    float4 al4 = ((const float4*)al)[tcol];
    float4 ar4 = ((const float4*)ar)[tcol];
#pragma unroll
    for (int r = 0; r < 4; r++) {
        int gr = row0 + trow * 4 + r;
        float pl = acc[r][0] * al4.x + acc[r][1] * al4.y + acc[r][2] * al4.z + acc[r][3] * al4.w;
        float pr = acc[r][0] * ar4.x + acc[r][1] * ar4.y + acc[r][2] * ar4.z + acc[r][3] * ar4.w;
        pl += __shfl_xor_sync(0xffffffffu, pl, 1);
        pl += __shfl_xor_sync(0xffffffffu, pl, 2);
        pr += __shfl_xor_sync(0xffffffffu, pr, 1);
        pr += __shfl_xor_sync(0xffffffffu, pr, 2);
        if (gr < NN) {
            if ((tcol & 3) == 0) {
                g_el[gr * HH + (tcol >> 2)] = pl;
                g_er[gr * HH + (tcol >> 2)] = pr;
            }
            __half2 p0 = __floats2half2_rn(acc[r][0], acc[r][1]);
            __half2 p1 = __floats2half2_rn(acc[r][2], acc[r][3]);
            uint2 pk;
            pk.x = *reinterpret_cast<unsigned*>(&p0);
            pk.y = *reinterpret_cast<unsigned*>(&p1);
            *reinterpret_cast<uint2*>(g_feath + (long)gr * HF + tcol * 4) = pk;
        }
    }
}

// ---------------- exclusive scan (single block, warp-shfl) --------------------
__global__ __launch_bounds__(1024) void scan_kernel() {
    __shared__ int wsum[32];
    __shared__ int carry_s;
    int lane = threadIdx.x & 31;
    int warp = threadIdx.x >> 5;
    if (threadIdx.x == 0) carry_s = 0;
    __syncthreads();
    for (int base = 0; base < NN; base += 1024) {
        int i = base + threadIdx.x;
        int v = (i < NN) ? g_cnt[i] : 0;
        int incl = v;
#pragma unroll
        for (int s = 1; s < 32; s <<= 1) {
            int t = __shfl_up_sync(0xffffffffu, incl, s);
            if (lane >= s) incl += t;
        }
        if (lane == 31) wsum[warp] = incl;
        __syncthreads();
        if (warp == 0) {
            int wv = wsum[lane];
            int wi = wv;
#pragma unroll
            for (int s = 1; s < 32; s <<= 1) {
                int t = __shfl_up_sync(0xffffffffu, wi, s);
                if (lane >= s) wi += t;
            }
            wsum[lane] = wi - wv;           // exclusive
        }
        __syncthreads();
        int excl = incl - v + wsum[warp] + carry_s;
        if (i < NN) { g_off[i] = excl; g_cursor[i] = excl; }
        __syncthreads();
        if (threadIdx.x == 1023) carry_s = excl + v;
        __syncthreads();
    }
    if (threadIdx.x == 0) g_off[NN] = carry_s;
}

// ---------------- scatter edges into CSR --------------------------------------
__global__ void scatter_kernel() {
    int stride = gridDim.x * blockDim.x;
    for (int i = blockIdx.x * blockDim.x + threadIdx.x; i < EE; i += stride) {
        int d = g_dst32[i];
        int p = atomicAdd(&g_cursor[d], 1);
        g_csr_src[p] = g_src32[i];
    }
}

// ---------------- fused softmax-aggregate + classifier ------------------------
// One warp per dst node; two 16-lane groups each process one edge (fp16 row =
// 128 half = 16 x uint4). Lanes sub<8 of each group own the per-head exp/sum.
__global__ __launch_bounds__(256) void agg_kernel(float* __restrict__ out) {
    int gtid = blockIdx.x * blockDim.x + threadIdx.x;
    int n    = gtid >> 5;
    int lane = gtid & 31;
    if (n >= NN) return;
    int half = lane >> 4;
    int sub  = lane & 15;
    unsigned gmask = half ? 0xFFFF0000u : 0x0000FFFFu;

    float ern = (sub < HH) ? g_er[n * HH + sub] : 0.f;
    int beg = g_off[n], end = g_off[n + 1];

    float acc[8];
#pragma unroll
    for (int k = 0; k < 8; k++) acc[k] = 0.f;
    float ssum = 0.f;

    for (int i = beg + half; i < end; i += 2) {
        int sv = g_csr_src[i];
        float exv = 0.f;
        if (sub < HH) {
            float e = g_el[sv * HH + sub] + ern;
            e = fmaxf(e, 0.f) + SLOPE * fminf(e, 0.f);
            exv = __expf(e);
            ssum += exv;
        }
        // lane sub covers cols 8*sub..8*sub+7; head = sub>>1
        float exh = __shfl_sync(gmask, exv, (half << 4) + (sub >> 1));
        uint4 f = *reinterpret_cast<const uint4*>(g_feath + (long)sv * HF + sub * 8);
        float2 v0 = __half22float2(*reinterpret_cast<__half2*>(&f.x));
        float2 v1 = __half22float2(*reinterpret_cast<__half2*>(&f.y));
        float2 v2 = __half22float2(*reinterpret_cast<__half2*>(&f.z));
        float2 v3 = __half22float2(*reinterpret_cast<__half2*>(&f.w));
        acc[0] += exh * v0.x; acc[1] += exh * v0.y;
        acc[2] += exh * v1.x; acc[3] += exh * v1.y;
        acc[4] += exh * v2.x; acc[5] += exh * v2.y;
        acc[6] += exh * v3.x; acc[7] += exh * v3.y;
    }
    __syncwarp();

    // combine the two halves
#pragma unroll
    for (int k = 0; k < 8; k++) acc[k] += __shfl_xor_sync(0xffffffffu, acc[k], 16);
    ssum += __shfl_xor_sync(0xffffffffu, ssum, 16);

    // normalize by the head's softmax sum
    float inv = 0.f;
    if (sub < HH) inv = 1.f / fmaxf(ssum, 1e-9f);
    float invh = __shfl_sync(0xffffffffu, inv, (half << 4) + (sub >> 1));
#pragma unroll
    for (int k = 0; k < 8; k++) acc[k] *= invh;

    // head-sum for the classifier: col = 8*sub+k, f = col & 15.
#pragma unroll
    for (int d = 2; d < 16; d <<= 1)
#pragma unroll
        for (int k = 0; k < 8; k++) acc[k] += __shfl_xor_sync(0xffffffffu, acc[k], d);

    if (lane < 2) {
        float4 o0, o1;
        o0.x = acc[0] * 0.125f + g_mbias[lane * 8 + 0];
        o0.y = acc[1] * 0.125f + g_mbias[lane * 8 + 1];
        o0.z = acc[2] * 0.125f + g_mbias[lane * 8 + 2];
        o0.w = acc[3] * 0.125f + g_mbias[lane * 8 + 3];
        o1.x = acc[4] * 0.125f + g_mbias[lane * 8 + 4];
        o1.y = acc[5] * 0.125f + g_mbias[lane * 8 + 5];
        o1.z = acc[6] * 0.125f + g_mbias[lane * 8 + 6];
        o1.w = acc[7] * 0.125f + g_mbias[lane * 8 + 7];
        ((float4*)out)[n * 4 + lane * 2 + 0] = o0;
        ((float4*)out)[n * 4 + lane * 2 + 1] = o1;
    }
}

// ---------------- launch ------------------------------------------------------
extern "C" void kernel_launch(void* const* d_in, const int* in_sizes, int n_in,
                              void* d_out, int out_size) {
    const float* x    = (const float*)d_in[0];
    const float* W    = (const float*)d_in[1];
    const float* al   = (const float*)d_in[2];
    const float* ar   = (const float*)d_in[3];
    const float* bias = (const float*)d_in[4];
    const void*  src  = d_in[5];
    const void*  dst  = d_in[6];
    float* out = (float*)d_out;

    detect_kernel<<<1, 32>>>(dst);
    zero_cnt_kernel<<<(NN + 255) / 256, 256>>>(bias);
    convert_hist_kernel<<<2048, 256>>>(src, dst);
    gemm_kernel<<<(NN + 31) / 32, 256>>>(x, W, al, ar);
    scan_kernel<<<1, 1024>>>();
    scatter_kernel<<<2048, 256>>>();
    agg_kernel<<<(NN * 32 + 255) / 256, 256>>>(out);
}